// round 13
// baseline (speedup 1.0000x reference)
#include <cuda_runtime.h>
#include <cuda_fp16.h>
#include <cstdint>
#include <math.h>

// ---------------- problem constants ----------------
#define BATCH    16384
#define F_IN     768
#define F_OUT    512
#define BM       64            // batch rows per CTA
#define BN       256           // output cols per CTA (N split across 2 CTAs)
#define BK       64            // K elements per chunk
#define NCHUNK   (F_IN / BK)   // 12 chunks per pass
#define TOTCHUNK (NCHUNK * 2)  // 24
#define NTHREADS 256
#define MTILES   (BATCH / BM)  // 256

// fixed-point scales: x = qx/2^14 (qx = xh*128+xl, 7-bit each)
//                     w = 0.5 * qw/2^14 (qw = wh*128+wl)
// preact = 0.5*hh/2^14 + 0.5*mid/2^21
#define C_HH  3.0517578125e-05f
#define C_MID 2.384185791015625e-07f

// ---------------- smem layout (bytes) ----------------
#define SM_RED   0                     // 64 f32
#define SM_A0    4096                  // 2 stages x 8192 (64 rows x [64B hi|64B lo])
#define SM_B     20480                 // 2 stages x 32768 (256 rows x 128B)
#define SM_TOTAL (SM_B + 2 * 32768)    // 86016

// ---------------- helpers ----------------
__device__ __forceinline__ uint32_t smem_u32(const void* p) {
    uint32_t a;
    asm("{ .reg .u64 t; cvta.to.shared.u64 t, %1; cvt.u32.u64 %0, t; }" : "=r"(a) : "l"(p));
    return a;
}

#define LDSM_X4(r0, r1, r2, r3, addr) \
    asm volatile("ldmatrix.sync.aligned.m8n8.x4.shared.b16 {%0,%1,%2,%3}, [%4];" \
                 : "=r"(r0), "=r"(r1), "=r"(r2), "=r"(r3) : "r"(addr))

// s8 x s8 -> s32 MMA, K=32
#define MMAS8(d, a, b) \
    asm volatile("mma.sync.aligned.m16n8k32.row.col.s32.s8.s8.s32 " \
                 "{%0,%1,%2,%3}, {%4,%5,%6,%7}, {%8,%9}, {%0,%1,%2,%3};" \
                 : "+r"((d)[0]), "+r"((d)[1]), "+r"((d)[2]), "+r"((d)[3]) \
                 : "r"((a)[0]), "r"((a)[1]), "r"((a)[2]), "r"((a)[3]), \
                   "r"((b)[0]), "r"((b)[1]))

#define CP_ASYNC16(dst, src) \
    asm volatile("cp.async.cg.shared.global [%0], [%1], 16;" :: "r"(dst), "l"(src) : "memory")
#define CP_COMMIT() asm volatile("cp.async.commit_group;" ::: "memory")
#define CP_WAIT0()  asm volatile("cp.async.wait_group 0;" ::: "memory")

// quantize 16 floats (x in [0,1)) -> 16B hi + 16B lo swizzled stores
__device__ __forceinline__ void quant_sts_a(uint32_t hiAddr, uint32_t loAddr, const float4* s) {
    uint32_t hi[4], lo[4];
#pragma unroll
    for (int j = 0; j < 4; ++j) {
        float4 v = s[j];
        int q0 = min(16383, max(0, __float2int_rn(v.x * 16384.0f)));
        int q1 = min(16383, max(0, __float2int_rn(v.y * 16384.0f)));
        int q2 = min(16383, max(0, __float2int_rn(v.z * 16384.0f)));
        int q3 = min(16383, max(0, __float2int_rn(v.w * 16384.0f)));
        hi[j] = (uint32_t)(q0 >> 7) | ((uint32_t)(q1 >> 7) << 8) |
                ((uint32_t)(q2 >> 7) << 16) | ((uint32_t)(q3 >> 7) << 24);
        lo[j] = (uint32_t)(q0 & 127) | ((uint32_t)(q1 & 127) << 8) |
                ((uint32_t)(q2 & 127) << 16) | ((uint32_t)(q3 & 127) << 24);
    }
    asm volatile("st.shared.v4.u32 [%0], {%1,%2,%3,%4};"
                 :: "r"(hiAddr), "r"(hi[0]), "r"(hi[1]), "r"(hi[2]), "r"(hi[3]) : "memory");
    asm volatile("st.shared.v4.u32 [%0], {%1,%2,%3,%4};"
                 :: "r"(loAddr), "r"(lo[0]), "r"(lo[1]), "r"(lo[2]), "r"(lo[3]) : "memory");
}

// ---------------- device globals ----------------
// W1 quantized: [n][chunk][64B hi | 64B lo]
__device__ __align__(16) int8_t g_W1q[F_OUT * NCHUNK * 128];
__device__ float g_part0[BATCH];
__device__ float g_part1[BATCH];

__global__ void __launch_bounds__(512) quant_w1_kernel(const float* __restrict__ W1) {
    const int i = blockIdx.x * 512 + threadIdx.x;   // 98304 threads, one float4 each
    const int n = i / 192;                          // 192 float4 per row of 768
    const int r = i - n * 192;
    const int c = r >> 4;                           // chunk (16 float4 per 64 k)
    const int ko = (r & 15) * 4;                    // byte offset within 64
    float4 v = reinterpret_cast<const float4*>(W1)[i];
    int q0 = min(16319, max(-16320, __float2int_rn(v.x * 32768.0f)));
    int q1 = min(16319, max(-16320, __float2int_rn(v.y * 32768.0f)));
    int q2 = min(16319, max(-16320, __float2int_rn(v.z * 32768.0f)));
    int q3 = min(16319, max(-16320, __float2int_rn(v.w * 32768.0f)));
    int h0 = (q0 + 64) >> 7, h1 = (q1 + 64) >> 7, h2 = (q2 + 64) >> 7, h3 = (q3 + 64) >> 7;
    int l0 = q0 - (h0 << 7), l1 = q1 - (h1 << 7), l2 = q2 - (h2 << 7), l3 = q3 - (h3 << 7);
    uint32_t hw = (uint32_t)(h0 & 255) | ((uint32_t)(h1 & 255) << 8) |
                  ((uint32_t)(h2 & 255) << 16) | ((uint32_t)(h3 & 255) << 24);
    uint32_t lw = (uint32_t)(l0 & 255) | ((uint32_t)(l1 & 255) << 8) |
                  ((uint32_t)(l2 & 255) << 16) | ((uint32_t)(l3 & 255) << 24);
    int8_t* base = g_W1q + ((size_t)n * NCHUNK + c) * 128 + ko;
    *reinterpret_cast<uint32_t*>(base)      = hw;
    *reinterpret_cast<uint32_t*>(base + 64) = lw;
}

__global__ void finalize_kernel(const float* __restrict__ b2, float* __restrict__ out) {
    int i = blockIdx.x * blockDim.x + threadIdx.x;
    if (i < BATCH) {
        float z = g_part0[i] + g_part1[i] + b2[0];
        out[i] = 1.0f / (1.0f + expf(-z));
    }
}

// ---------------- fused perspective-network kernel (int8 dual-word) ----------------
// grid (256, 2): x = M tile, y = N half. 8 warps: warpM = wid>>2, warpN = wid&3.
// Warp tile 32 x 64. Three s8 products: hh, (hl+lh) share acc_mid.
__global__ void __launch_bounds__(NTHREADS, 1)
persp_kernel(const float* __restrict__ stm, const float* __restrict__ nstm,
             const float* __restrict__ b1, const float* __restrict__ W2) {
    extern __shared__ __align__(1024) char smem[];
    const uint32_t sb = smem_u32(smem);
    const int tid  = threadIdx.x;
    const int lane = tid & 31;
    const int wid  = tid >> 5;
    const int warpM = wid >> 2;    // 0..1
    const int warpN = wid & 3;     // 0..3
    const int m0  = blockIdx.x * BM;
    const int nb0 = blockIdx.y * BN;

    float* red_s = reinterpret_cast<float*>(smem + SM_RED);
    if (tid < BM) red_s[tid] = 0.0f;

    // ---- ldmatrix per-lane geometry (cols xored with row-swizzle) ----
    const int inRowA = ((lane >> 3) & 1) * 8 + (lane & 7);
    const uint32_t aColX = (((uint32_t)(lane >> 4)) * 16) ^ (((uint32_t)(lane & 7)) << 4);
    const uint32_t aOffBase = (uint32_t)(warpM * 32 + inRowA) * 128;
    const int inRowB = ((lane >> 4) & 1) * 8 + (lane & 7);
    const uint32_t bColX = ((((uint32_t)(lane >> 3)) & 1) * 16) ^ (((uint32_t)(lane & 7)) << 4);
    const uint32_t bOffBase = (uint32_t)(warpN * 64 + inRowB) * 128;

    // ---- fill geometry ----
    // A: 64 rows, thread -> row tid>>2, 16 x-values at (tid&3)*16
    const int aRowG = tid >> 2;
    const int aSeg  = tid & 3;
    const uint32_t aRowXor = ((uint32_t)(aRowG & 7)) << 4;
    const uint32_t aHiOff = (uint32_t)aRowG * 128 + (((uint32_t)aSeg * 16)      ^ aRowXor);
    const uint32_t aLoOff = (uint32_t)aRowG * 128 + (((uint32_t)aSeg * 16 + 64) ^ aRowXor);
    // B: 256 rows x 128B per stage; thread -> rows (tid>>3)+32j (j<8), seg tid&7
    const int bRow0 = tid >> 3;            // 0..31
    const int bSeg  = tid & 7;

    int acc_hh[2][8][4]  = {};
    int acc_mid[2][8][4] = {};
    float rowsum[4] = {0.f, 0.f, 0.f, 0.f};
    float4 sA[4];    // staged A floats for chunk g+1

    // ---- prologue: B chunk 0 via cp.async; A chunk 0 quant; stage A chunk 1 ----
    {
#pragma unroll
        for (int j = 0; j < 8; ++j) {
            const int row = bRow0 + 32 * j;
            const uint32_t dst = sb + SM_B + (uint32_t)row * 128 +
                                 (((uint32_t)bSeg * 16) ^ (((uint32_t)(row & 7)) << 4));
            CP_ASYNC16(dst, g_W1q + ((size_t)(nb0 + row) * NCHUNK + 0) * 128 + bSeg * 16);
        }
        CP_COMMIT();
        const float4* s0 = reinterpret_cast<const float4*>(
            stm + (size_t)(m0 + aRowG) * F_IN + aSeg * 16);
        float4 t[4] = { s0[0], s0[1], s0[2], s0[3] };
        quant_sts_a(sb + SM_A0 + aHiOff, sb + SM_A0 + aLoOff, t);
        const float4* s1 = reinterpret_cast<const float4*>(
            stm + (size_t)(m0 + aRowG) * F_IN + BK + aSeg * 16);
        sA[0] = s1[0]; sA[1] = s1[1]; sA[2] = s1[2]; sA[3] = s1[3];
        CP_WAIT0();
        __syncthreads();
    }

    for (int g = 0; g < TOTCHUNK; ++g) {
        const int p = g & 1;
        const uint32_t bufA  = sb + SM_A0 + p * 8192;
        const uint32_t bufB  = sb + SM_B  + p * 32768;
        const uint32_t bufAn = sb + SM_A0 + (p ^ 1) * 8192;
        const uint32_t bufBn = sb + SM_B  + (p ^ 1) * 32768;

        // prefetch chunk g+1
        if (g + 1 < TOTCHUNK) {
            const int c1 = (g + 1) % NCHUNK;
#pragma unroll
            for (int j = 0; j < 8; ++j) {
                const int row = bRow0 + 32 * j;
                const uint32_t dst = bufBn + (uint32_t)row * 128 +
                                     (((uint32_t)bSeg * 16) ^ (((uint32_t)(row & 7)) << 4));
                CP_ASYNC16(dst, g_W1q + ((size_t)(nb0 + row) * NCHUNK + c1) * 128 + bSeg * 16);
            }
            CP_COMMIT();
            quant_sts_a(bufAn + aHiOff, bufAn + aLoOff, sA);
        }
        // LDG chunk g+2 into staging registers
        if (g + 2 < TOTCHUNK) {
            const int g2 = g + 2;
            const float* X = (g2 >= NCHUNK) ? nstm : stm;
            const float4* s = reinterpret_cast<const float4*>(
                X + (size_t)(m0 + aRowG) * F_IN + (g2 % NCHUNK) * BK + aSeg * 16);
            sA[0] = s[0]; sA[1] = s[1]; sA[2] = s[2]; sA[3] = s[3];
        }

        // ---- compute chunk g: 2 k32-steps x {hh, hl, lh} ----
#pragma unroll
        for (int ks = 0; ks < 2; ++ks) {
            const uint32_t kxh = (uint32_t)(ks * 32);        // hi cols 0..63
            const uint32_t kxl = (uint32_t)(64 + ks * 32);   // lo cols 64..127
            uint32_t Ah[2][4], Al[2][4];
#pragma unroll
            for (int mt = 0; mt < 2; ++mt) {
                LDSM_X4(Ah[mt][0], Ah[mt][1], Ah[mt][2], Ah[mt][3],
                        bufA + aOffBase + mt * 2048 + (aColX ^ kxh));
                LDSM_X4(Al[mt][0], Al[mt][1], Al[mt][2], Al[mt][3],
                        bufA + aOffBase + mt * 2048 + (aColX ^ kxl));
            }
            uint32_t Bh[8][2], Bl[8][2];
#pragma unroll
            for (int nt2 = 0; nt2 < 4; ++nt2) {
                uint32_t r0, r1, r2, r3;
                LDSM_X4(r0, r1, r2, r3, bufB + bOffBase + nt2 * 2048 + (bColX ^ kxh));
                Bh[nt2 * 2][0] = r0;     Bh[nt2 * 2][1] = r1;
                Bh[nt2 * 2 + 1][0] = r2; Bh[nt2 * 2 + 1][1] = r3;
                LDSM_X4(r0, r1, r2, r3, bufB + bOffBase + nt2 * 2048 + (bColX ^ kxl));
                Bl[nt2 * 2][0] = r0;     Bl[nt2 * 2][1] = r1;
                Bl[nt2 * 2 + 1][0] = r2; Bl[nt2 * 2 + 1][1] = r3;
            }
#pragma unroll
            for (int mt = 0; mt < 2; ++mt)
#pragma unroll
                for (int nt = 0; nt < 8; ++nt) {
                    MMAS8(acc_hh[mt][nt],  Ah[mt], Bh[nt]);
                    MMAS8(acc_mid[mt][nt], Ah[mt], Bl[nt]);
                    MMAS8(acc_mid[mt][nt], Al[mt], Bh[nt]);
                }
        }

        // ---- end-of-pass: dequant + bias + clip + W2 partial dot, reset acc ----
        if (g == NCHUNK - 1 || g == TOTCHUNK - 1) {
            const int w2o = (g >= NCHUNK) ? F_OUT : 0;
#pragma unroll
            for (int mt = 0; mt < 2; ++mt) {
#pragma unroll
                for (int nt = 0; nt < 8; ++nt) {
                    const int gn = nb0 + warpN * 64 + nt * 8 + (lane & 3) * 2;
                    const float2 bv = __ldg(reinterpret_cast<const float2*>(b1 + gn));
                    const float2 wv = __ldg(reinterpret_cast<const float2*>(W2 + w2o + gn));
                    float pre, h;
                    pre = __int2float_rn(acc_hh[mt][nt][0]) * C_HH + __int2float_rn(acc_mid[mt][nt][0]) * C_MID;
                    h = fminf(fmaxf(pre + bv.x, 0.f), 1.f); rowsum[mt*2+0] = fmaf(h, wv.x, rowsum[mt*2+0]);
                    pre = __int2float_rn(acc_hh[mt][nt][1]) * C_HH + __int2float_rn(acc_mid[mt][nt][1]) * C_MID;
                    h = fminf(fmaxf(pre + bv.y, 0.f), 1.f); rowsum[mt*2+0] = fmaf(h, wv.y, rowsum[mt*2+0]);
                    pre = __int2float_rn(acc_hh[mt][nt][2]) * C_HH + __int2float_rn(acc_mid[mt][nt][2]) * C_MID;
                    h = fminf(fmaxf(pre + bv.x, 0.f), 1.f); rowsum[mt*2+1] = fmaf(h, wv.x, rowsum[mt*2+1]);
                    pre = __int2float_rn(acc_hh[mt][nt][3]) * C_HH + __int2float_rn(acc_mid[mt][nt][3]) * C_MID;
                    h = fminf(fmaxf(pre + bv.y, 0.f), 1.f); rowsum[mt*2+1] = fmaf(h, wv.y, rowsum[mt*2+1]);
#pragma unroll
                    for (int q = 0; q < 4; ++q) { acc_hh[mt][nt][q] = 0; acc_mid[mt][nt][q] = 0; }
                }
            }
        }

        CP_WAIT0();
        __syncthreads();
    }

    // ---- cross-lane + cross-warp reduce, write partial ----
#pragma unroll
    for (int r = 0; r < 4; ++r) {
        float v = rowsum[r];
        v += __shfl_xor_sync(0xFFFFFFFFu, v, 1);
        v += __shfl_xor_sync(0xFFFFFFFFu, v, 2);
        if ((lane & 3) == 0) {
            const int row = warpM * 32 + (r >> 1) * 16 + (r & 1) * 8 + (lane >> 2);
            atomicAdd(&red_s[row], v);
        }
    }
    __syncthreads();
    if (tid < BM) {
        float* gp = blockIdx.y ? g_part1 : g_part0;
        gp[m0 + tid] = red_s[tid];
    }
}

// ---------------- launch ----------------
extern "C" void kernel_launch(void* const* d_in, const int* in_sizes, int n_in,
                              void* d_out, int out_size) {
    const float* stm  = (const float*)d_in[0];
    const float* nstm = (const float*)d_in[1];
    const float* W1   = (const float*)d_in[2];
    const float* b1   = (const float*)d_in[3];
    const float* W2   = (const float*)d_in[4];
    const float* b2   = (const float*)d_in[5];
    float* out = (float*)d_out;

    cudaFuncSetAttribute(persp_kernel, cudaFuncAttributeMaxDynamicSharedMemorySize, SM_TOTAL);

    quant_w1_kernel<<<192, 512>>>(W1);                 // 98304 threads, one float4 each
    persp_kernel<<<dim3(MTILES, 2), NTHREADS, SM_TOTAL>>>(stm, nstm, b1, W2);
    finalize_kernel<<<(BATCH + 255) / 256, 256>>>(b2, out);
}

// round 14
// speedup vs baseline: 7.2688x; 7.2688x over previous
#include <cuda_runtime.h>
#include <cuda_fp16.h>
#include <cstdint>
#include <math.h>

// ---------------- problem constants ----------------
#define BATCH    16384
#define F_IN     768
#define F_OUT    512
#define BM       64            // batch rows per CTA
#define BK       64            // K chunk
#define NCHUNK   (F_IN / BK)   // 12 chunks per pass
#define NPASS    2
#define TOTCHUNK (NCHUNK * NPASS)  // 24
#define NTHREADS 512
#define CTAS     (BATCH / BM)  // 256

// ---------------- smem layout (bytes) ----------------
#define SM_BIAS  0                     // 512 f32 = 2048
#define SM_W2    2048                  // 1024 f32 = 4096
#define SM_RED   6144                  // 64 f32 = 256
#define SM_A0    8192                  // 64 rows x 128B = 8192
#define SM_A1    16384
#define SM_B0    24576                 // 512 rows x 128B = 65536
#define SM_B1    90112
#define SM_TOTAL 155648

// ---------------- helpers ----------------
__device__ __forceinline__ uint32_t smem_u32(const void* p) {
    uint32_t a;
    asm("{ .reg .u64 t; cvta.to.shared.u64 t, %1; cvt.u32.u64 %0, t; }" : "=r"(a) : "l"(p));
    return a;
}

#define LDSM_X4(r0, r1, r2, r3, addr) \
    asm volatile("ldmatrix.sync.aligned.m8n8.x4.shared.b16 {%0,%1,%2,%3}, [%4];" \
                 : "=r"(r0), "=r"(r1), "=r"(r2), "=r"(r3) : "r"(addr))

#define MMA16816(d, a, b) \
    asm volatile("mma.sync.aligned.m16n8k16.row.col.f32.f16.f16.f32 " \
                 "{%0,%1,%2,%3}, {%4,%5,%6,%7}, {%8,%9}, {%0,%1,%2,%3};" \
                 : "+f"((d)[0]), "+f"((d)[1]), "+f"((d)[2]), "+f"((d)[3]) \
                 : "r"((a)[0]), "r"((a)[1]), "r"((a)[2]), "r"((a)[3]), \
                   "r"((b)[0]), "r"((b)[1]))

#define CP_ASYNC16(dst, src) \
    asm volatile("cp.async.cg.shared.global [%0], [%1], 16;" :: "r"(dst), "l"(src) : "memory")
#define CP_COMMIT() asm volatile("cp.async.commit_group;" ::: "memory")
#define CP_WAIT0()  asm volatile("cp.async.wait_group 0;" ::: "memory")

// cvt 8 f32 -> 8 f16, one swizzled 16B STS
__device__ __forceinline__ void sts_a16(uint32_t addr, float4 v0, float4 v1) {
    uint32_t u0, u1, u2, u3;
    asm("cvt.rn.f16x2.f32 %0, %1, %2;" : "=r"(u0) : "f"(v0.y), "f"(v0.x));
    asm("cvt.rn.f16x2.f32 %0, %1, %2;" : "=r"(u1) : "f"(v0.w), "f"(v0.z));
    asm("cvt.rn.f16x2.f32 %0, %1, %2;" : "=r"(u2) : "f"(v1.y), "f"(v1.x));
    asm("cvt.rn.f16x2.f32 %0, %1, %2;" : "=r"(u3) : "f"(v1.w), "f"(v1.z));
    asm volatile("st.shared.v4.u32 [%0], {%1,%2,%3,%4};"
                 :: "r"(addr), "r"(u0), "r"(u1), "r"(u2), "r"(u3) : "memory");
}

// ---------------- W1 fp32 -> fp16 pre-conversion (MLP=4: 4 independent float4/thread) ----------------
__device__ __align__(16) __half g_W1h[F_OUT * F_IN];

__global__ void __launch_bounds__(512) convert_w1_kernel(const float* __restrict__ W1) {
    // 48 blocks x 512 threads x 4 float4 = 98304 float4 = F_OUT*F_IN/4
    const int base = blockIdx.x * 2048 + threadIdx.x;
    float4 v0 = reinterpret_cast<const float4*>(W1)[base];
    float4 v1 = reinterpret_cast<const float4*>(W1)[base + 512];
    float4 v2 = reinterpret_cast<const float4*>(W1)[base + 1024];
    float4 v3 = reinterpret_cast<const float4*>(W1)[base + 1536];
    __half2* dst = reinterpret_cast<__half2*>(g_W1h);
    dst[(base)        * 2]     = __floats2half2_rn(v0.x, v0.y);
    dst[(base)        * 2 + 1] = __floats2half2_rn(v0.z, v0.w);
    dst[(base + 512)  * 2]     = __floats2half2_rn(v1.x, v1.y);
    dst[(base + 512)  * 2 + 1] = __floats2half2_rn(v1.z, v1.w);
    dst[(base + 1024) * 2]     = __floats2half2_rn(v2.x, v2.y);
    dst[(base + 1024) * 2 + 1] = __floats2half2_rn(v2.z, v2.w);
    dst[(base + 1536) * 2]     = __floats2half2_rn(v3.x, v3.y);
    dst[(base + 1536) * 2 + 1] = __floats2half2_rn(v3.z, v3.w);
}

// ---------------- fused perspective-network kernel (exact R4 structure, proven best) ----------------
// 16 warps: warpM = wid>>3 (2 x 32 rows), warpN = wid&7 (8 x 64 cols).
__global__ void __launch_bounds__(NTHREADS, 1)
persp_kernel(const float* __restrict__ stm, const float* __restrict__ nstm,
             const float* __restrict__ b1, const float* __restrict__ W2,
             const float* __restrict__ b2, float* __restrict__ out) {
    extern __shared__ __align__(1024) char smem[];
    const uint32_t sb = smem_u32(smem);
    const int tid  = threadIdx.x;
    const int lane = tid & 31;
    const int wid  = tid >> 5;
    const int warpM = wid >> 3;    // 0..1
    const int warpN = wid & 7;     // 0..7
    const int m0 = blockIdx.x * BM;

    float* bias_s = reinterpret_cast<float*>(smem + SM_BIAS);
    float* w2_s   = reinterpret_cast<float*>(smem + SM_W2);
    float* red_s  = reinterpret_cast<float*>(smem + SM_RED);

    for (int i = tid; i < F_OUT; i += NTHREADS)     bias_s[i] = b1[i];
    for (int i = tid; i < 2 * F_OUT; i += NTHREADS) w2_s[i]   = W2[i];
    if (tid < BM) red_s[tid] = 0.0f;

    // ---- ldmatrix per-lane geometry ----
    const int aRow   = warpM * 32 + ((lane >> 3) & 1) * 8 + (lane & 7);
    const uint32_t aXor = ((uint32_t)(lane >> 4) * 16) ^ ((uint32_t)(aRow & 7) << 4);
    const uint32_t aOff = aRow * 128;
    const int bRow   = warpN * 64 + ((lane >> 4) & 1) * 8 + (lane & 7);
    const uint32_t bXor = (((uint32_t)(lane >> 3) & 1) * 16) ^ ((uint32_t)(bRow & 7) << 4);
    const uint32_t bOff = bRow * 128;

    // ---- global->smem fill geometry ----
    const int aRowG = tid >> 3;             // 0..63
    const int aSeg  = tid & 7;              // 8-float segment
    const uint32_t aSts = aRowG * 128 + (((uint32_t)aSeg * 16) ^ ((uint32_t)(aRowG & 7) << 4));
    const int bRow0 = tid >> 3;             // 0..63, rows bRow0 + 64*j
    const int bSeg  = tid & 7;
    const uint32_t bDstBase = bRow0 * 128 + (((uint32_t)bSeg * 16) ^ ((uint32_t)(bRow0 & 7) << 4));
    const __half* bSrcBase = g_W1h + (size_t)bRow0 * F_IN + bSeg * 8;

    float acc[2][8][4] = {};
    float rowsum[4] = {0.f, 0.f, 0.f, 0.f};
    float4 sA0, sA1;   // staged A regs (chunk g+1)

    // ---- prologue: fill buf0 (chunk 0), stage A(chunk 1) ----
    {
        const uint32_t bufB = sb + SM_B0;
#pragma unroll
        for (int j = 0; j < 8; ++j)
            CP_ASYNC16(bufB + bDstBase + j * 8192, bSrcBase + (size_t)j * 64 * F_IN);
        CP_COMMIT();
        const float4* s0 = reinterpret_cast<const float4*>(
            stm + (size_t)(m0 + aRowG) * F_IN + aSeg * 8);
        sts_a16(sb + SM_A0 + aSts, s0[0], s0[1]);
        const float4* s1 = reinterpret_cast<const float4*>(
            stm + (size_t)(m0 + aRowG) * F_IN + 1 * BK + aSeg * 8);
        sA0 = s1[0]; sA1 = s1[1];
        CP_WAIT0();
        __syncthreads();
    }

    for (int g = 0; g < TOTCHUNK; ++g) {
        const int p = g & 1;
        const uint32_t bufA  = sb + (p ? SM_A1 : SM_A0);
        const uint32_t bufB  = sb + (p ? SM_B1 : SM_B0);
        const uint32_t bufAn = sb + (p ? SM_A0 : SM_A1);
        const uint32_t bufBn = sb + (p ? SM_B0 : SM_B1);

        // prefetch chunk g+1: staged A -> smem, B via cp.async
        if (g + 1 < TOTCHUNK) {
            sts_a16(bufAn + aSts, sA0, sA1);
            const int c1 = (g + 1) % NCHUNK;
            const __half* src = bSrcBase + c1 * BK;
#pragma unroll
            for (int j = 0; j < 8; ++j)
                CP_ASYNC16(bufBn + bDstBase + j * 8192, src + (size_t)j * 64 * F_IN);
            CP_COMMIT();
        }
        // LDG chunk g+2 into staging (lands during compute)
        if (g + 2 < TOTCHUNK) {
            const int g2 = g + 2;
            const float* X = (g2 >= NCHUNK) ? nstm : stm;
            const int c2 = g2 % NCHUNK;
            const float4* s = reinterpret_cast<const float4*>(
                X + (size_t)(m0 + aRowG) * F_IN + c2 * BK + aSeg * 8);
            sA0 = s[0]; sA1 = s[1];
        }

        // ---- compute chunk g from buf p ----
#pragma unroll
        for (int ks = 0; ks < 4; ++ks) {
            const uint32_t kx = (uint32_t)(ks << 5);
            uint32_t a0[4], a1[4];
            LDSM_X4(a0[0], a0[1], a0[2], a0[3], bufA + aOff +        (aXor ^ kx));
            LDSM_X4(a1[0], a1[1], a1[2], a1[3], bufA + aOff + 2048 + (aXor ^ kx));
            uint32_t b[8][2];
#pragma unroll
            for (int nt2 = 0; nt2 < 4; ++nt2) {
                uint32_t r0, r1, r2, r3;
                LDSM_X4(r0, r1, r2, r3, bufB + bOff + nt2 * 2048 + (bXor ^ kx));
                b[nt2 * 2][0] = r0; b[nt2 * 2][1] = r1;
                b[nt2 * 2 + 1][0] = r2; b[nt2 * 2 + 1][1] = r3;
            }
#pragma unroll
            for (int nt = 0; nt < 8; ++nt) {
                MMA16816(acc[0][nt], a0, b[nt]);
                MMA16816(acc[1][nt], a1, b[nt]);
            }
        }

        // ---- end-of-pass epilogue: bias + clip + W2 partial dot, reset acc ----
        if (g == NCHUNK - 1 || g == TOTCHUNK - 1) {
            const int pass = (g >= NCHUNK);
            const int w2o = pass * F_OUT;
#pragma unroll
            for (int mt = 0; mt < 2; ++mt) {
#pragma unroll
                for (int nt = 0; nt < 8; ++nt) {
                    const int nb = warpN * 64 + nt * 8 + (lane & 3) * 2;
                    const float ba = bias_s[nb],      bb = bias_s[nb + 1];
                    const float wa = w2_s[w2o + nb],  wb = w2_s[w2o + nb + 1];
                    float h;
                    h = fminf(fmaxf(acc[mt][nt][0] + ba, 0.f), 1.f); rowsum[mt*2+0] = fmaf(h, wa, rowsum[mt*2+0]);
                    h = fminf(fmaxf(acc[mt][nt][1] + bb, 0.f), 1.f); rowsum[mt*2+0] = fmaf(h, wb, rowsum[mt*2+0]);
                    h = fminf(fmaxf(acc[mt][nt][2] + ba, 0.f), 1.f); rowsum[mt*2+1] = fmaf(h, wa, rowsum[mt*2+1]);
                    h = fminf(fmaxf(acc[mt][nt][3] + bb, 0.f), 1.f); rowsum[mt*2+1] = fmaf(h, wb, rowsum[mt*2+1]);
                    acc[mt][nt][0] = 0.f; acc[mt][nt][1] = 0.f;
                    acc[mt][nt][2] = 0.f; acc[mt][nt][3] = 0.f;
                }
            }
        }

        CP_WAIT0();
        __syncthreads();
    }

    // ---- cross-lane + cross-warp reduce, sigmoid, store ----
#pragma unroll
    for (int r = 0; r < 4; ++r) {
        float v = rowsum[r];
        v += __shfl_xor_sync(0xFFFFFFFFu, v, 1);
        v += __shfl_xor_sync(0xFFFFFFFFu, v, 2);
        if ((lane & 3) == 0) {
            const int row = warpM * 32 + (r >> 1) * 16 + (r & 1) * 8 + (lane >> 2);
            atomicAdd(&red_s[row], v);
        }
    }
    __syncthreads();
    if (tid < BM) {
        const float z = red_s[tid] + b2[0];
        out[m0 + tid] = 1.0f / (1.0f + expf(-z));
    }
}

// ---------------- launch ----------------
extern "C" void kernel_launch(void* const* d_in, const int* in_sizes, int n_in,
                              void* d_out, int out_size) {
    const float* stm  = (const float*)d_in[0];
    const float* nstm = (const float*)d_in[1];
    const float* W1   = (const float*)d_in[2];
    const float* b1   = (const float*)d_in[3];
    const float* W2   = (const float*)d_in[4];
    const float* b2   = (const float*)d_in[5];
    float* out = (float*)d_out;

    cudaFuncSetAttribute(persp_kernel, cudaFuncAttributeMaxDynamicSharedMemorySize, SM_TOTAL);

    convert_w1_kernel<<<48, 512>>>(W1);   // 48*512*4 float4 = full W1
    persp_kernel<<<CTAS, NTHREADS, SM_TOTAL>>>(stm, nstm, b1, W2, b2, out);
}